// round 5
// baseline (speedup 1.0000x reference)
#include <cuda_runtime.h>

#define N_NODES 100000
#define N_EDGES 1250000
#define IN_DIM 64
#define HID 128
#define OUT_DIM 64
#define N_PAD 100032   // 1563 * 64, pads node dim to a multiple of the GEMM row tile

// Scratch (device globals; zero-initialized at module load — padded rows stay 0
// forever because all stores below are guarded by row < N_NODES).
// float4-typed so RED.v4 / float4 loads are guaranteed 16B-aligned.
__device__ float4 g_agg[N_NODES * IN_DIM / 4];
__device__ float  g_deg[N_NODES];
__device__ float4 g_h0[N_PAD * HID / 4];
__device__ float4 g_h1[N_PAD * HID / 4];

// ---------------------------------------------------------------------------
// Zero the accumulation buffers (graph is replayed, so must re-zero each call)
// ---------------------------------------------------------------------------
__global__ void zero_kernel() {
    int i = blockIdx.x * blockDim.x + threadIdx.x;
    if (i < N_NODES * IN_DIM / 4) g_agg[i] = make_float4(0.f, 0.f, 0.f, 0.f);
    if (i < N_NODES) g_deg[i] = 0.0f;
}

// ---------------------------------------------------------------------------
// Edge scatter: agg[row] += x[col] (vector f32x4 reductions), deg[row] += 1
// One thread per (edge, 16B chunk): 20M threads, 20M RED.v4 ops.
// Indices are int32 (harness converts the reference's int64).
// ---------------------------------------------------------------------------
__global__ void scatter_kernel(const int* __restrict__ ei,
                               const float* __restrict__ x) {
    int t = blockIdx.x * blockDim.x + threadIdx.x;
    if (t >= N_EDGES * 16) return;
    int e = t >> 4;
    int c = t & 15;
    int dst = ei[e];            // row
    int src = ei[N_EDGES + e];  // col
    if ((unsigned)dst >= N_NODES || (unsigned)src >= N_NODES) return;
    const float4* x4 = (const float4*)x;
    float4 v = __ldg(&x4[src * 16 + c]);
    float4* p = &g_agg[dst * 16 + c];
    asm volatile("red.global.add.v4.f32 [%0], {%1, %2, %3, %4};"
                 :: "l"(p), "f"(v.x), "f"(v.y), "f"(v.z), "f"(v.w)
                 : "memory");
    if (c == 0) atomicAdd(&g_deg[dst], 1.0f);
}

// ---------------------------------------------------------------------------
// h0 = concat(x, agg / max(deg,1))   [N, 128]
// ---------------------------------------------------------------------------
__global__ void build_h0(const float* __restrict__ x) {
    int t = blockIdx.x * blockDim.x + threadIdx.x;
    if (t >= N_NODES * 32) return;
    int n = t >> 5;
    int c = t & 31;
    float4 v;
    if (c < 16) {
        v = ((const float4*)x)[n * 16 + c];
    } else {
        float inv = 1.0f / fmaxf(g_deg[n], 1.0f);
        float4 a = g_agg[n * 16 + (c - 16)];
        v = make_float4(a.x * inv, a.y * inv, a.z * inv, a.w * inv);
    }
    g_h0[n * 32 + c] = v;
}

// ---------------------------------------------------------------------------
// One MLP layer: C[N, MOUT] = act(A[N,128] @ W[128,MOUT] + b)
// Block: 64 rows x MOUT cols, full K=128 staged in smem.
// 256 threads, each computes 4 rows x (MOUT/16) cols in registers.
// smem: sA transposed [k][row] 32KB + sW [k][m] (64KB or 32KB) -> dynamic.
// ---------------------------------------------------------------------------
template <int MOUT, bool RELU>
__global__ void mlp_layer(const float* __restrict__ A,
                          const float* __restrict__ W,
                          const float* __restrict__ bias,
                          float* __restrict__ C) {
    constexpr int CPT = MOUT / 16;  // cols per thread: 8 (HID) or 4 (OUT)
    extern __shared__ float smem[];
    float* sA = smem;               // [128][64]
    float* sW = smem + 128 * 64;    // [128][MOUT]

    const int tid = threadIdx.x;
    const int R = blockIdx.x * 64;

    // Stage A tile (64 rows x 128 k), transposed to sA[k][row]
    {
        int row = tid >> 2;
        int kb = (tid & 3) * 32;
        const float* ap = A + (size_t)(R + row) * HID + kb;
#pragma unroll
        for (int j = 0; j < 8; j++) {
            float4 v = *(const float4*)(ap + j * 4);
            sA[(kb + j * 4 + 0) * 64 + row] = v.x;
            sA[(kb + j * 4 + 1) * 64 + row] = v.y;
            sA[(kb + j * 4 + 2) * 64 + row] = v.z;
            sA[(kb + j * 4 + 3) * 64 + row] = v.w;
        }
    }
    // Stage full W
    {
        constexpr int TOT = 128 * MOUT / 4;  // float4 count (4096 or 2048)
        const float4* w4 = (const float4*)W;
        float4* s4 = (float4*)sW;
        for (int i = tid; i < TOT; i += 256) s4[i] = w4[i];
    }
    __syncthreads();

    const int ty = tid >> 4;   // 0..15 -> row group (4 rows)
    const int tx = tid & 15;   // 0..15 -> col group (CPT cols)
    const int c0 = tx * CPT;

    float acc[4][CPT];
#pragma unroll
    for (int r = 0; r < 4; r++)
#pragma unroll
        for (int m = 0; m < CPT; m++) acc[r][m] = 0.0f;

#pragma unroll 4
    for (int k = 0; k < 128; k++) {
        float4 av = *(const float4*)(sA + k * 64 + ty * 4);
        float a0 = av.x, a1 = av.y, a2 = av.z, a3 = av.w;
        float w[CPT];
#pragma unroll
        for (int m = 0; m < CPT; m += 4) {
            float4 wv = *(const float4*)(sW + k * MOUT + c0 + m);
            w[m + 0] = wv.x; w[m + 1] = wv.y; w[m + 2] = wv.z; w[m + 3] = wv.w;
        }
#pragma unroll
        for (int m = 0; m < CPT; m++) {
            acc[0][m] = fmaf(a0, w[m], acc[0][m]);
            acc[1][m] = fmaf(a1, w[m], acc[1][m]);
            acc[2][m] = fmaf(a2, w[m], acc[2][m]);
            acc[3][m] = fmaf(a3, w[m], acc[3][m]);
        }
    }

    float bv[CPT];
#pragma unroll
    for (int m = 0; m < CPT; m++) bv[m] = bias[c0 + m];

#pragma unroll
    for (int r = 0; r < 4; r++) {
        int gr = R + ty * 4 + r;
        if (gr < N_NODES) {
#pragma unroll
            for (int m = 0; m < CPT; m += 4) {
                float4 o;
                o.x = acc[r][m + 0] + bv[m + 0];
                o.y = acc[r][m + 1] + bv[m + 1];
                o.z = acc[r][m + 2] + bv[m + 2];
                o.w = acc[r][m + 3] + bv[m + 3];
                if (RELU) {
                    o.x = fmaxf(o.x, 0.0f); o.y = fmaxf(o.y, 0.0f);
                    o.z = fmaxf(o.z, 0.0f); o.w = fmaxf(o.w, 0.0f);
                }
                *(float4*)(C + (size_t)gr * MOUT + c0 + m) = o;
            }
        }
    }
}

// ---------------------------------------------------------------------------
extern "C" void kernel_launch(void* const* d_in, const int* in_sizes, int n_in,
                              void* d_out, int out_size) {
    const float* x  = (const float*)d_in[0];
    const int*   ei = (const int*)d_in[1];     // edge_index as int32
    const float* W1 = (const float*)d_in[2];
    const float* b1 = (const float*)d_in[3];
    const float* W2 = (const float*)d_in[4];
    const float* b2 = (const float*)d_in[5];
    const float* W3 = (const float*)d_in[6];
    const float* b3 = (const float*)d_in[7];
    const float* W4 = (const float*)d_in[8];
    const float* b4 = (const float*)d_in[9];
    float* out      = (float*)d_out;

    void* h0p_v; void* h1p_v;
    cudaGetSymbolAddress(&h0p_v, g_h0);
    cudaGetSymbolAddress(&h1p_v, g_h1);
    float* h0p = (float*)h0p_v;
    float* h1p = (float*)h1p_v;

    const int SMEM_HID = (128 * 64 + 128 * 128) * 4;  // 98304
    const int SMEM_OUT = (128 * 64 + 128 * 64) * 4;   // 65536
    cudaFuncSetAttribute(mlp_layer<128, true>,
                         cudaFuncAttributeMaxDynamicSharedMemorySize, SMEM_HID);
    cudaFuncSetAttribute(mlp_layer<64, false>,
                         cudaFuncAttributeMaxDynamicSharedMemorySize, SMEM_OUT);

    zero_kernel<<<(N_NODES * IN_DIM / 4 + 255) / 256, 256>>>();
    scatter_kernel<<<(N_EDGES * 16 + 255) / 256, 256>>>(ei, x);
    build_h0<<<(N_NODES * 32 + 255) / 256, 256>>>(x);

    const int NBLK = N_PAD / 64;  // 1563
    mlp_layer<128, true ><<<NBLK, 256, SMEM_HID>>>(h0p, W1, b1, h1p);
    mlp_layer<128, true ><<<NBLK, 256, SMEM_HID>>>(h1p, W2, b2, h0p);
    mlp_layer<128, true ><<<NBLK, 256, SMEM_HID>>>(h0p, W3, b3, h1p);
    mlp_layer<64,  false><<<NBLK, 256, SMEM_OUT>>>(h1p, W4, b4, out);
}

// round 8
// speedup vs baseline: 2.2291x; 2.2291x over previous
#include <cuda_runtime.h>
#include <cuda_bf16.h>

#define N_NODES 100000
#define N_EDGES 1250000
#define IN_DIM 64
#define HID 128
#define OUT_DIM 64
#define NT 782                 // row tiles of 128: 782*128 = 100096 >= N_NODES
#define TILE_F4 2048           // one 128x128 bf16 plane tile = 32KB = 2048 float4

typedef unsigned int u32;

// ---------------------------------------------------------------------------
// Device scratch (zero-initialized at load; pad rows beyond N_NODES in g_Ahi/
// g_Alo are never written by build_h0 -> stay zero).
// Activations: row-major bf16 planes [NT*128][128], hi/lo split, ping-pong A/B.
// ---------------------------------------------------------------------------
__device__ float4 g_agg[N_NODES * IN_DIM / 4];
__device__ float  g_deg[N_NODES];
__device__ float4 g_Ahi[NT * TILE_F4], g_Alo[NT * TILE_F4];
__device__ float4 g_Bhi[NT * TILE_F4], g_Blo[NT * TILE_F4];
// weight images Wt[n][k] bf16, hi/lo: W1@0, W2@2048, W3@4096, W4@6144 (float4 offs)
__device__ float4 g_Whi[3 * 2048 + 1024], g_Wlo[3 * 2048 + 1024];

// ---------------------------------------------------------------------------
__device__ __forceinline__ u32 smem_u32(const void* p) {
    u32 a;
    asm("{ .reg .u64 t; cvta.to.shared.u64 t, %1; cvt.u32.u64 %0, t; }"
        : "=r"(a) : "l"(p));
    return a;
}
__device__ __forceinline__ u32 pack_hi(float a, float b) {
    __nv_bfloat162 p;
    p.x = __float2bfloat16(a); p.y = __float2bfloat16(b);
    return reinterpret_cast<u32&>(p);
}
__device__ __forceinline__ float bf16_rt(float v) {
    return __bfloat162float(__float2bfloat16(v));
}

#define LDSM_X4(r0, r1, r2, r3, addr)                                          \
    asm volatile("ldmatrix.sync.aligned.m8n8.x4.shared.b16 {%0,%1,%2,%3}, [%4];" \
                 : "=r"(r0), "=r"(r1), "=r"(r2), "=r"(r3) : "r"(addr))

#define MMA16816(d, a, b0, b1)                                                 \
    asm volatile("mma.sync.aligned.m16n8k16.row.col.f32.bf16.bf16.f32 "        \
                 "{%0,%1,%2,%3}, {%4,%5,%6,%7}, {%8,%9}, {%0,%1,%2,%3};"       \
                 : "+f"((d)[0]), "+f"((d)[1]), "+f"((d)[2]), "+f"((d)[3])      \
                 : "r"((a)[0]), "r"((a)[1]), "r"((a)[2]), "r"((a)[3]),         \
                   "r"(b0), "r"(b1))

// ---------------------------------------------------------------------------
// Zero the accumulation buffers (graph is replayed; must re-zero each call)
// ---------------------------------------------------------------------------
__global__ void zero_kernel() {
    int i = blockIdx.x * blockDim.x + threadIdx.x;
    if (i < N_NODES * 16) g_agg[i] = make_float4(0.f, 0.f, 0.f, 0.f);
    if (i < N_NODES) g_deg[i] = 0.0f;
}

// ---------------------------------------------------------------------------
// Edge scatter: agg[row] += x[col] (RED.v4), deg[row] += 1
// ---------------------------------------------------------------------------
__global__ void scatter_kernel(const int* __restrict__ ei,
                               const float* __restrict__ x) {
    int t = blockIdx.x * blockDim.x + threadIdx.x;
    if (t >= N_EDGES * 16) return;
    int e = t >> 4;
    int c = t & 15;
    int dst = ei[e];
    int src = ei[N_EDGES + e];
    if ((unsigned)dst >= N_NODES || (unsigned)src >= N_NODES) return;
    const float4* x4 = (const float4*)x;
    float4 v = __ldg(&x4[src * 16 + c]);
    float4* p = &g_agg[dst * 16 + c];
    asm volatile("red.global.add.v4.f32 [%0], {%1, %2, %3, %4};"
                 :: "l"(p), "f"(v.x), "f"(v.y), "f"(v.z), "f"(v.w) : "memory");
    if (c == 0) atomicAdd(&g_deg[dst], 1.0f);
}

// ---------------------------------------------------------------------------
// h0 = concat(x, agg/max(deg,1)) -> row-major bf16 hi/lo planes
// ---------------------------------------------------------------------------
__global__ void build_h0(const float* __restrict__ x) {
    int t = blockIdx.x * blockDim.x + threadIdx.x;
    if (t >= N_NODES * 16) return;
    int n = t >> 4;
    int c0 = (t & 15) * 8;
    const float4* x4 = (const float4*)x;
    float v[8];
    if (c0 < 64) {
        float4 a = x4[n * 16 + c0 / 4];
        float4 b = x4[n * 16 + c0 / 4 + 1];
        v[0]=a.x; v[1]=a.y; v[2]=a.z; v[3]=a.w; v[4]=b.x; v[5]=b.y; v[6]=b.z; v[7]=b.w;
    } else {
        float inv = 1.0f / fmaxf(g_deg[n], 1.0f);
        float4 a = g_agg[n * 16 + (c0 - 64) / 4];
        float4 b = g_agg[n * 16 + (c0 - 64) / 4 + 1];
        v[0]=a.x*inv; v[1]=a.y*inv; v[2]=a.z*inv; v[3]=a.w*inv;
        v[4]=b.x*inv; v[5]=b.y*inv; v[6]=b.z*inv; v[7]=b.w*inv;
    }
    u32 hw[4], lw[4];
#pragma unroll
    for (int i = 0; i < 4; i++) {
        float a = v[2*i], b = v[2*i+1];
        hw[i] = pack_hi(a, b);
        lw[i] = pack_hi(a - bf16_rt(a), b - bf16_rt(b));
    }
    int f4i = n * 16 + c0 / 8;           // row-major: 16 float4 per 128-col row
    g_Ahi[f4i] = *(float4*)hw;
    g_Alo[f4i] = *(float4*)lw;
}

// ---------------------------------------------------------------------------
// Weight prep: W[k][n] -> Wt[n][k] bf16 hi/lo planes (row-major, 128 k-cols)
// ---------------------------------------------------------------------------
__global__ void wprep(const float* __restrict__ W1, const float* __restrict__ W2,
                      const float* __restrict__ W3, const float* __restrict__ W4) {
    int i = blockIdx.x * blockDim.x + threadIdx.x;
    const float* W; int MOUT; int base; int idx;
    if      (i < 16384) { W = W1; MOUT = 128; base = 0;     idx = i; }
    else if (i < 32768) { W = W2; MOUT = 128; base = 16384; idx = i - 16384; }
    else if (i < 49152) { W = W3; MOUT = 128; base = 32768; idx = i - 32768; }
    else if (i < 57344) { W = W4; MOUT = 64;  base = 49152; idx = i - 49152; }
    else return;
    int k = idx / MOUT, n = idx % MOUT;
    float v = W[idx];
    int off = base + n * 128 + k;        // bf16 element offset
    __nv_bfloat16 h = __float2bfloat16(v);
    ((__nv_bfloat16*)g_Whi)[off] = h;
    ((__nv_bfloat16*)g_Wlo)[off] = __float2bfloat16(v - __bfloat162float(h));
}

// ---------------------------------------------------------------------------
// HMMA GEMM layer: C[128, MOUT] = act(A_tile[128,128] @ W[128,MOUT] + b)
// Split-bf16: D = Ahi*Bhi + Alo*Bhi + Ahi*Blo (fp32 accumulators).
// smem tiles padded to 136 bf16/row (272B) -> conflict-free ldmatrix.
// 8 warps in 4x2: warp tile 32 rows x (MOUT/2) cols.
// ---------------------------------------------------------------------------
template <int MOUT, bool RELU, bool LAST>
__global__ __launch_bounds__(256, 1) void gemm_layer(
    const float4* __restrict__ Ah, const float4* __restrict__ Al,
    const float4* __restrict__ Wh, const float4* __restrict__ Wl,
    const float* __restrict__ bias,
    u32* __restrict__ Dh, u32* __restrict__ Dl,
    float* __restrict__ out)
{
    constexpr int SROW = 272;            // smem row stride (bytes)
    constexpr int A_HI = 0;
    constexpr int A_LO = 128 * SROW;                 // 34816
    constexpr int B_HI = 2 * 128 * SROW;             // 69632
    constexpr int B_LO = B_HI + MOUT * SROW;
    constexpr int BIAS = B_LO + MOUT * SROW;
    constexpr int NTILES = MOUT / 16;                // n-tiles per warp (8 or 4)

    extern __shared__ char smem[];
    const u32 sb = smem_u32(smem);
    float* sbias = (float*)(smem + BIAS);

    const int tid = threadIdx.x;
    const int tile = blockIdx.x;

    // ---- stage A hi/lo and B hi/lo (strided float4 copies) ----
    {
        const float4* sAh = Ah + (size_t)tile * TILE_F4;
        const float4* sAl = Al + (size_t)tile * TILE_F4;
#pragma unroll
        for (int i = tid; i < TILE_F4; i += 256) {
            int row = i >> 4, seg = i & 15;
            *(float4*)(smem + A_HI + row * SROW + seg * 16) = sAh[i];
            *(float4*)(smem + A_LO + row * SROW + seg * 16) = sAl[i];
        }
        constexpr int BF4 = MOUT * 16;
#pragma unroll
        for (int i = tid; i < BF4; i += 256) {
            int row = i >> 4, seg = i & 15;
            *(float4*)(smem + B_HI + row * SROW + seg * 16) = Wh[i];
            *(float4*)(smem + B_LO + row * SROW + seg * 16) = Wl[i];
        }
        if (tid < MOUT) sbias[tid] = bias[tid];
    }
    __syncthreads();

    const int lane = tid & 31, w = tid >> 5;
    const int m0 = (w & 3) * 32;
    const int n0 = (w >> 2) * (MOUT / 2);
    const int lrow = lane & 15, lcol = lane >> 4;
    const u32 frag_off = (u32)(lrow * SROW + lcol * 16);

    float acc[2][NTILES][4];
#pragma unroll
    for (int mt = 0; mt < 2; mt++)
#pragma unroll
        for (int nt = 0; nt < NTILES; nt++)
#pragma unroll
            for (int q = 0; q < 4; q++) acc[mt][nt][q] = 0.0f;

    const u32 aHi0 = sb + A_HI + m0 * SROW + frag_off;
    const u32 aLo0 = sb + A_LO + m0 * SROW + frag_off;
    const u32 bHi0 = sb + B_HI + n0 * SROW + frag_off;
    const u32 bLo0 = sb + B_LO + n0 * SROW + frag_off;

#pragma unroll
    for (int ks = 0; ks < 8; ks++) {
        const u32 koff = ks * 32;        // 16 bf16 = 32 bytes
        u32 ah[2][4], al[2][4];
#pragma unroll
        for (int mt = 0; mt < 2; mt++) {
            LDSM_X4(ah[mt][0], ah[mt][1], ah[mt][2], ah[mt][3],
                    aHi0 + mt * 16 * SROW + koff);
            LDSM_X4(al[mt][0], al[mt][1], al[mt][2], al[mt][3],
                    aLo0 + mt * 16 * SROW + koff);
        }
#pragma unroll
        for (int p = 0; p < NTILES / 2; p++) {
            u32 bh[4], bl[4];
            LDSM_X4(bh[0], bh[1], bh[2], bh[3], bHi0 + p * 16 * SROW + koff);
            LDSM_X4(bl[0], bl[1], bl[2], bl[3], bLo0 + p * 16 * SROW + koff);
#pragma unroll
            for (int mt = 0; mt < 2; mt++) {
                MMA16816(acc[mt][2*p],   ah[mt], bh[0], bh[2]);
                MMA16816(acc[mt][2*p],   al[mt], bh[0], bh[2]);
                MMA16816(acc[mt][2*p],   ah[mt], bl[0], bl[2]);
                MMA16816(acc[mt][2*p+1], ah[mt], bh[1], bh[3]);
                MMA16816(acc[mt][2*p+1], al[mt], bh[1], bh[3]);
                MMA16816(acc[mt][2*p+1], ah[mt], bl[1], bl[3]);
            }
        }
    }

    // ---- epilogue: bias (+relu), then pack next-layer planes or fp32 out ----
#pragma unroll
    for (int mt = 0; mt < 2; mt++) {
#pragma unroll
        for (int nt = 0; nt < NTILES; nt++) {
            int gr0 = tile * 128 + m0 + mt * 16 + (lane >> 2);
            int gr1 = gr0 + 8;
            int cg = n0 + nt * 8 + (lane & 3) * 2;
            float b0 = sbias[cg], b1 = sbias[cg + 1];
            float v0 = acc[mt][nt][0] + b0, v1 = acc[mt][nt][1] + b1;
            float v2 = acc[mt][nt][2] + b0, v3 = acc[mt][nt][3] + b1;
            if (RELU) {
                v0 = fmaxf(v0, 0.f); v1 = fmaxf(v1, 0.f);
                v2 = fmaxf(v2, 0.f); v3 = fmaxf(v3, 0.f);
            }
            if (LAST) {
                if (gr0 < N_NODES)
                    *(float2*)(out + (size_t)gr0 * OUT_DIM + cg) = make_float2(v0, v1);
                if (gr1 < N_NODES)
                    *(float2*)(out + (size_t)gr1 * OUT_DIM + cg) = make_float2(v2, v3);
            } else {
                size_t i0 = (size_t)gr0 * 64 + (cg >> 1);
                size_t i1 = (size_t)gr1 * 64 + (cg >> 1);
                Dh[i0] = pack_hi(v0, v1);
                Dl[i0] = pack_hi(v0 - bf16_rt(v0), v1 - bf16_rt(v1));
                Dh[i1] = pack_hi(v2, v3);
                Dl[i1] = pack_hi(v2 - bf16_rt(v2), v3 - bf16_rt(v3));
            }
        }
    }
}

// ---------------------------------------------------------------------------
extern "C" void kernel_launch(void* const* d_in, const int* in_sizes, int n_in,
                              void* d_out, int out_size) {
    const float* x  = (const float*)d_in[0];
    const int*   ei = (const int*)d_in[1];
    const float* W1 = (const float*)d_in[2];
    const float* b1 = (const float*)d_in[3];
    const float* W2 = (const float*)d_in[4];
    const float* b2 = (const float*)d_in[5];
    const float* W3 = (const float*)d_in[6];
    const float* b3 = (const float*)d_in[7];
    const float* W4 = (const float*)d_in[8];
    const float* b4 = (const float*)d_in[9];
    float* out      = (float*)d_out;

    void *ahp, *alp, *bhp, *blp, *whp, *wlp;
    cudaGetSymbolAddress(&ahp, g_Ahi); cudaGetSymbolAddress(&alp, g_Alo);
    cudaGetSymbolAddress(&bhp, g_Bhi); cudaGetSymbolAddress(&blp, g_Blo);
    cudaGetSymbolAddress(&whp, g_Whi); cudaGetSymbolAddress(&wlp, g_Wlo);
    float4* Ahi = (float4*)ahp; float4* Alo = (float4*)alp;
    float4* Bhi = (float4*)bhp; float4* Blo = (float4*)blp;
    float4* Whi = (float4*)whp; float4* Wlo = (float4*)wlp;

    const int SMEM_HID = 2 * 128 * 272 + 2 * 128 * 272 + 512;  // 139776
    const int SMEM_OUT = 2 * 128 * 272 + 2 * 64 * 272 + 256;   // 104704
    cudaFuncSetAttribute(gemm_layer<128, true, false>,
                         cudaFuncAttributeMaxDynamicSharedMemorySize, SMEM_HID);
    cudaFuncSetAttribute(gemm_layer<64, false, true>,
                         cudaFuncAttributeMaxDynamicSharedMemorySize, SMEM_OUT);

    zero_kernel<<<(N_NODES * 16 + 255) / 256, 256>>>();
    scatter_kernel<<<(N_EDGES * 16 + 255) / 256, 256>>>(ei, x);
    build_h0<<<(N_NODES * 16 + 255) / 256, 256>>>(x);
    wprep<<<(57344 + 255) / 256, 256>>>(W1, W2, W3, W4);

    // L1: bufA -> bufB ; L2: bufB -> bufA ; L3: bufA -> bufB ; L4: bufB -> out
    gemm_layer<128, true, false><<<NT, 256, SMEM_HID>>>(
        Ahi, Alo, Whi + 0,    Wlo + 0,    b1, (u32*)Bhi, (u32*)Blo, nullptr);
    gemm_layer<128, true, false><<<NT, 256, SMEM_HID>>>(
        Bhi, Blo, Whi + 2048, Wlo + 2048, b2, (u32*)Ahi, (u32*)Alo, nullptr);
    gemm_layer<128, true, false><<<NT, 256, SMEM_HID>>>(
        Ahi, Alo, Whi + 4096, Wlo + 4096, b3, (u32*)Bhi, (u32*)Blo, nullptr);
    gemm_layer<64, false, true><<<NT, 256, SMEM_OUT>>>(
        Bhi, Blo, Whi + 6144, Wlo + 6144, b4, nullptr, nullptr, out);
}

// round 10
// speedup vs baseline: 2.6348x; 1.1820x over previous
#include <cuda_runtime.h>
#include <cuda_bf16.h>

#define N_NODES 100000
#define N_EDGES 1250000
#define IN_DIM 64
#define HID 128
#define OUT_DIM 64
#define NT 782                 // row tiles of 128: 782*128 = 100096 >= N_NODES

typedef unsigned int u32;

// ---------------------------------------------------------------------------
// Device scratch (zero-initialized at load).
// ---------------------------------------------------------------------------
__device__ float4 g_agg[N_NODES * IN_DIM / 4];
__device__ float  g_deg[N_NODES];
// weight images Wt[n][k] bf16 hi/lo planes: W1@0, W2@2048, W3@4096, W4@6144 (float4)
__device__ float4 g_Whi[3 * 2048 + 1024], g_Wlo[3 * 2048 + 1024];

// ---------------------------------------------------------------------------
__device__ __forceinline__ u32 smem_u32(const void* p) {
    u32 a;
    asm("{ .reg .u64 t; cvta.to.shared.u64 t, %1; cvt.u32.u64 %0, t; }"
        : "=r"(a) : "l"(p));
    return a;
}
__device__ __forceinline__ u32 pack_hi(float a, float b) {
    __nv_bfloat162 p;
    p.x = __float2bfloat16(a); p.y = __float2bfloat16(b);
    return reinterpret_cast<u32&>(p);
}
__device__ __forceinline__ float bf16_rt(float v) {
    return __bfloat162float(__float2bfloat16(v));
}

#define LDSM_X4(r0, r1, r2, r3, addr)                                          \
    asm volatile("ldmatrix.sync.aligned.m8n8.x4.shared.b16 {%0,%1,%2,%3}, [%4];" \
                 : "=r"(r0), "=r"(r1), "=r"(r2), "=r"(r3) : "r"(addr))

#define MMA16816(d, a, b0, b1)                                                 \
    asm volatile("mma.sync.aligned.m16n8k16.row.col.f32.bf16.bf16.f32 "        \
                 "{%0,%1,%2,%3}, {%4,%5,%6,%7}, {%8,%9}, {%0,%1,%2,%3};"       \
                 : "+f"((d)[0]), "+f"((d)[1]), "+f"((d)[2]), "+f"((d)[3])      \
                 : "r"((a)[0]), "r"((a)[1]), "r"((a)[2]), "r"((a)[3]),         \
                   "r"(b0), "r"(b1))

// smem layout (bytes); SROW = 272 (136 bf16) -> conflict-free ldmatrix
#define SROW 272
#define A_HI 0
#define A_LO (128 * SROW)                 // 34816
#define W_HI (2 * 128 * SROW)             // 69632
#define W_LO (3 * 128 * SROW)             // 104448
#define BIAS (4 * 128 * SROW)             // 139264
#define SMEM_TOTAL (BIAS + 512)           // 139776

// ---------------------------------------------------------------------------
// prep kernel: zero accumulators (blocks [0, ZBLK)) + weight conversion
// (blocks [ZBLK, ZBLK+WBLK)). W[k][n] -> Wt[n][k] bf16 hi/lo planes.
// ---------------------------------------------------------------------------
#define ZBLK 6250   // ceil(1.6e6 / 256)
#define WBLK 224    // ceil(57344 / 256)
__global__ void prep_kernel(const float* __restrict__ W1, const float* __restrict__ W2,
                            const float* __restrict__ W3, const float* __restrict__ W4) {
    if (blockIdx.x < ZBLK) {
        int i = blockIdx.x * blockDim.x + threadIdx.x;
        if (i < N_NODES * 16) g_agg[i] = make_float4(0.f, 0.f, 0.f, 0.f);
        if (i < N_NODES) g_deg[i] = 0.0f;
        return;
    }
    int i = (blockIdx.x - ZBLK) * blockDim.x + threadIdx.x;
    const float* W; int MOUT; int base; int idx;
    if      (i < 16384) { W = W1; MOUT = 128; base = 0;     idx = i; }
    else if (i < 32768) { W = W2; MOUT = 128; base = 16384; idx = i - 16384; }
    else if (i < 49152) { W = W3; MOUT = 128; base = 32768; idx = i - 32768; }
    else if (i < 57344) { W = W4; MOUT = 64;  base = 49152; idx = i - 49152; }
    else return;
    int k = idx / MOUT, n = idx % MOUT;
    float v = W[idx];
    int off = base + n * 128 + k;        // bf16 element offset
    __nv_bfloat16 h = __float2bfloat16(v);
    ((__nv_bfloat16*)g_Whi)[off] = h;
    ((__nv_bfloat16*)g_Wlo)[off] = __float2bfloat16(v - __bfloat162float(h));
}

// ---------------------------------------------------------------------------
// Edge scatter: agg[row] += x[col] (RED.v4), deg[row] += 1
// ---------------------------------------------------------------------------
__global__ void scatter_kernel(const int* __restrict__ ei,
                               const float* __restrict__ x) {
    int t = blockIdx.x * blockDim.x + threadIdx.x;
    if (t >= N_EDGES * 16) return;
    int e = t >> 4;
    int c = t & 15;
    int dst = ei[e];
    int src = ei[N_EDGES + e];
    if ((unsigned)dst >= N_NODES || (unsigned)src >= N_NODES) return;
    const float4* x4 = (const float4*)x;
    float4 v = __ldg(&x4[src * 16 + c]);
    float4* p = &g_agg[dst * 16 + c];
    asm volatile("red.global.add.v4.f32 [%0], {%1, %2, %3, %4};"
                 :: "l"(p), "f"(v.x), "f"(v.y), "f"(v.z), "f"(v.w) : "memory");
    if (c == 0) atomicAdd(&g_deg[dst], 1.0f);
}

// ---------------------------------------------------------------------------
// One MLP layer executed in-smem. A planes live at A_HI/A_LO; W staged into
// W_HI/W_LO from global. Split-bf16: D = Ahi*Bhi + Alo*Bhi + Ahi*Blo.
// Epilogue: LAST -> fp32 to out; else repack bf16 hi/lo into the A buffers.
// ---------------------------------------------------------------------------
template <int MOUT, bool RELU, bool LAST>
__device__ __forceinline__ void layer_step(
    char* smem, u32 sb,
    const float4* __restrict__ Wh, const float4* __restrict__ Wl,
    const float* __restrict__ bias, float* __restrict__ out, int tile)
{
    constexpr int NTILES = MOUT / 16;
    const int tid = threadIdx.x;

    // ---- stage W hi/lo + bias ----
    {
        constexpr int BF4 = MOUT * 16;
#pragma unroll
        for (int i = tid; i < BF4; i += 256) {
            int row = i >> 4, seg = i & 15;
            *(float4*)(smem + W_HI + row * SROW + seg * 16) = Wh[i];
            *(float4*)(smem + W_LO + row * SROW + seg * 16) = Wl[i];
        }
        if (tid < MOUT) ((float*)(smem + BIAS))[tid] = bias[tid];
    }
    __syncthreads();

    const int lane = tid & 31, w = tid >> 5;
    const int m0 = (w & 3) * 32;
    const int n0 = (w >> 2) * (MOUT / 2);
    const u32 frag_off = (u32)((lane & 15) * SROW + (lane >> 4) * 16);

    float acc[2][NTILES][4];
#pragma unroll
    for (int mt = 0; mt < 2; mt++)
#pragma unroll
        for (int nt = 0; nt < NTILES; nt++)
#pragma unroll
            for (int q = 0; q < 4; q++) acc[mt][nt][q] = 0.0f;

    const u32 aHi0 = sb + A_HI + m0 * SROW + frag_off;
    const u32 aLo0 = sb + A_LO + m0 * SROW + frag_off;
    const u32 bHi0 = sb + W_HI + n0 * SROW + frag_off;
    const u32 bLo0 = sb + W_LO + n0 * SROW + frag_off;

#pragma unroll
    for (int ks = 0; ks < 8; ks++) {
        const u32 koff = ks * 32;        // 16 bf16 = 32 bytes
        u32 ah[2][4], al[2][4];
#pragma unroll
        for (int mt = 0; mt < 2; mt++) {
            LDSM_X4(ah[mt][0], ah[mt][1], ah[mt][2], ah[mt][3],
                    aHi0 + mt * 16 * SROW + koff);
            LDSM_X4(al[mt][0], al[mt][1], al[mt][2], al[mt][3],
                    aLo0 + mt * 16 * SROW + koff);
        }
#pragma unroll
        for (int p = 0; p < NTILES / 2; p++) {
            u32 bh[4], bl[4];
            LDSM_X4(bh[0], bh[1], bh[2], bh[3], bHi0 + p * 16 * SROW + koff);
            LDSM_X4(bl[0], bl[1], bl[2], bl[3], bLo0 + p * 16 * SROW + koff);
#pragma unroll
            for (int mt = 0; mt < 2; mt++) {
                MMA16816(acc[mt][2*p],   ah[mt], bh[0], bh[2]);
                MMA16816(acc[mt][2*p],   al[mt], bh[0], bh[2]);
                MMA16816(acc[mt][2*p],   ah[mt], bl[0], bl[2]);
                MMA16816(acc[mt][2*p+1], ah[mt], bh[1], bh[3]);
                MMA16816(acc[mt][2*p+1], al[mt], bh[1], bh[3]);
                MMA16816(acc[mt][2*p+1], ah[mt], bl[1], bl[3]);
            }
        }
    }
    __syncthreads();   // all A/W reads done; safe to overwrite A (and W next layer)

    // ---- epilogue ----
    const float* sbias = (const float*)(smem + BIAS);
#pragma unroll
    for (int mt = 0; mt < 2; mt++) {
#pragma unroll
        for (int nt = 0; nt < NTILES; nt++) {
            int r0 = m0 + mt * 16 + (lane >> 2);
            int r1 = r0 + 8;
            int cg = n0 + nt * 8 + (lane & 3) * 2;
            float b0 = sbias[cg], b1 = sbias[cg + 1];
            float v0 = acc[mt][nt][0] + b0, v1 = acc[mt][nt][1] + b1;
            float v2 = acc[mt][nt][2] + b0, v3 = acc[mt][nt][3] + b1;
            if (RELU) {
                v0 = fmaxf(v0, 0.f); v1 = fmaxf(v1, 0.f);
                v2 = fmaxf(v2, 0.f); v3 = fmaxf(v3, 0.f);
            }
            if (LAST) {
                int gr0 = tile * 128 + r0, gr1 = tile * 128 + r1;
                if (gr0 < N_NODES)
                    *(float2*)(out + (size_t)gr0 * OUT_DIM + cg) = make_float2(v0, v1);
                if (gr1 < N_NODES)
                    *(float2*)(out + (size_t)gr1 * OUT_DIM + cg) = make_float2(v2, v3);
            } else {
                *(u32*)(smem + A_HI + r0 * SROW + cg * 2) = pack_hi(v0, v1);
                *(u32*)(smem + A_LO + r0 * SROW + cg * 2) =
                    pack_hi(v0 - bf16_rt(v0), v1 - bf16_rt(v1));
                *(u32*)(smem + A_HI + r1 * SROW + cg * 2) = pack_hi(v2, v3);
                *(u32*)(smem + A_LO + r1 * SROW + cg * 2) =
                    pack_hi(v2 - bf16_rt(v2), v3 - bf16_rt(v3));
            }
        }
    }
    // next layer's post-stage __syncthreads orders these writes before its reads
}

// ---------------------------------------------------------------------------
// Fused MLP: per 128-row tile, build h0 planes in smem, then 4 layers in-smem.
// ---------------------------------------------------------------------------
__global__ __launch_bounds__(256, 1) void fused_mlp(
    const float* __restrict__ x,
    const float4* __restrict__ Wh, const float4* __restrict__ Wl,
    const float* __restrict__ b1, const float* __restrict__ b2,
    const float* __restrict__ b3, const float* __restrict__ b4,
    float* __restrict__ out)
{
    extern __shared__ char smem[];
    const u32 sb = smem_u32(smem);
    const int tid = threadIdx.x;
    const int tile = blockIdx.x;

    // ---- prologue: h0 = concat(x, agg/max(deg,1)) -> bf16 hi/lo planes in smem
    const float4* x4 = (const float4*)x;
#pragma unroll
    for (int i = tid; i < 128 * 16; i += 256) {
        int r = i >> 4;
        int c0 = (i & 15) * 8;
        int gr = tile * 128 + r;
        float v[8];
        if (gr < N_NODES) {
            if (c0 < 64) {
                float4 a = x4[(size_t)gr * 16 + c0 / 4];
                float4 b = x4[(size_t)gr * 16 + c0 / 4 + 1];
                v[0]=a.x; v[1]=a.y; v[2]=a.z; v[3]=a.w;
                v[4]=b.x; v[5]=b.y; v[6]=b.z; v[7]=b.w;
            } else {
                float inv = 1.0f / fmaxf(g_deg[gr], 1.0f);
                float4 a = g_agg[(size_t)gr * 16 + (c0 - 64) / 4];
                float4 b = g_agg[(size_t)gr * 16 + (c0 - 64) / 4 + 1];
                v[0]=a.x*inv; v[1]=a.y*inv; v[2]=a.z*inv; v[3]=a.w*inv;
                v[4]=b.x*inv; v[5]=b.y*inv; v[6]=b.z*inv; v[7]=b.w*inv;
            }
        } else {
#pragma unroll
            for (int q = 0; q < 8; q++) v[q] = 0.0f;
        }
        u32 hw[4], lw[4];
#pragma unroll
        for (int q = 0; q < 4; q++) {
            float a = v[2*q], b = v[2*q+1];
            hw[q] = pack_hi(a, b);
            lw[q] = pack_hi(a - bf16_rt(a), b - bf16_rt(b));
        }
        *(float4*)(smem + A_HI + r * SROW + c0 * 2) = *(float4*)hw;
        *(float4*)(smem + A_LO + r * SROW + c0 * 2) = *(float4*)lw;
    }
    // (layer_step's post-stage __syncthreads orders the prologue writes too)

    layer_step<128, true,  false>(smem, sb, Wh + 0,    Wl + 0,    b1, nullptr, tile);
    layer_step<128, true,  false>(smem, sb, Wh + 2048, Wl + 2048, b2, nullptr, tile);
    layer_step<128, true,  false>(smem, sb, Wh + 4096, Wl + 4096, b3, nullptr, tile);
    layer_step<64,  false, true >(smem, sb, Wh + 6144, Wl + 6144, b4, out,     tile);
}

// ---------------------------------------------------------------------------
extern "C" void kernel_launch(void* const* d_in, const int* in_sizes, int n_in,
                              void* d_out, int out_size) {
    const float* x  = (const float*)d_in[0];
    const int*   ei = (const int*)d_in[1];
    const float* W1 = (const float*)d_in[2];
    const float* b1 = (const float*)d_in[3];
    const float* W2 = (const float*)d_in[4];
    const float* b2 = (const float*)d_in[5];
    const float* W3 = (const float*)d_in[6];
    const float* b3 = (const float*)d_in[7];
    const float* W4 = (const float*)d_in[8];
    const float* b4 = (const float*)d_in[9];
    float* out      = (float*)d_out;

    void *whp, *wlp;
    cudaGetSymbolAddress(&whp, g_Whi);
    cudaGetSymbolAddress(&wlp, g_Wlo);
    float4* Wh = (float4*)whp;
    float4* Wl = (float4*)wlp;

    cudaFuncSetAttribute(fused_mlp,
                         cudaFuncAttributeMaxDynamicSharedMemorySize, SMEM_TOTAL);

    prep_kernel<<<ZBLK + WBLK, 256>>>(W1, W2, W3, W4);
    scatter_kernel<<<(N_EDGES * 16 + 255) / 256, 256>>>(ei, x);
    fused_mlp<<<NT, 256, SMEM_TOTAL>>>(x, Wh, Wl, b1, b2, b3, b4, out);
}

// round 13
// speedup vs baseline: 2.9375x; 1.1149x over previous
#include <cuda_runtime.h>
#include <cuda_bf16.h>

#define N_NODES 100000
#define N_EDGES 1250000
#define IN_DIM 64
#define HID 128
#define OUT_DIM 64
#define NT 782                 // row tiles of 128: 782*128 = 100096 >= N_NODES

typedef unsigned int u32;

// ---------------------------------------------------------------------------
// Device scratch (zero-initialized at load).
// ---------------------------------------------------------------------------
__device__ float4 g_agg[N_NODES * IN_DIM / 4];
__device__ float  g_deg[N_NODES];
// weight images Wt[n][k] bf16 hi/lo planes: W1@0, W2@2048, W3@4096, W4@6144 (float4)
__device__ float4 g_Whi[3 * 2048 + 1024], g_Wlo[3 * 2048 + 1024];

// ---------------------------------------------------------------------------
__device__ __forceinline__ u32 smem_u32(const void* p) {
    u32 a;
    asm("{ .reg .u64 t; cvta.to.shared.u64 t, %1; cvt.u32.u64 %0, t; }"
        : "=r"(a) : "l"(p));
    return a;
}
__device__ __forceinline__ u32 pack_hi(float a, float b) {
    __nv_bfloat162 p;
    p.x = __float2bfloat16(a); p.y = __float2bfloat16(b);
    return reinterpret_cast<u32&>(p);
}
__device__ __forceinline__ float bf16_rt(float v) {
    return __bfloat162float(__float2bfloat16(v));
}

#define LDSM_X4(r0, r1, r2, r3, addr)                                          \
    asm volatile("ldmatrix.sync.aligned.m8n8.x4.shared.b16 {%0,%1,%2,%3}, [%4];" \
                 : "=r"(r0), "=r"(r1), "=r"(r2), "=r"(r3) : "r"(addr))

#define MMA16816(d, a, b0, b1)                                                 \
    asm volatile("mma.sync.aligned.m16n8k16.row.col.f32.bf16.bf16.f32 "        \
                 "{%0,%1,%2,%3}, {%4,%5,%6,%7}, {%8,%9}, {%0,%1,%2,%3};"       \
                 : "+f"((d)[0]), "+f"((d)[1]), "+f"((d)[2]), "+f"((d)[3])      \
                 : "r"((a)[0]), "r"((a)[1]), "r"((a)[2]), "r"((a)[3]),         \
                   "r"(b0), "r"(b1))

// smem layout (bytes); SROW = 272 (136 bf16) -> conflict-free ldmatrix
#define SROW 272
#define A_HI 0
#define A_LO (128 * SROW)                 // 34816
#define W_HI (2 * 128 * SROW)             // 69632
#define W_LO (3 * 128 * SROW)             // 104448
#define BIAS (4 * 128 * SROW)             // 139264
#define SMEM_TOTAL (BIAS + 512)           // 139776

#define NTHREADS 512

// ---------------------------------------------------------------------------
// prep kernel: zero accumulators (blocks [0, ZBLK)) + weight conversion
// (blocks [ZBLK, ZBLK+WBLK)). W[k][n] -> Wt[n][k] bf16 hi/lo planes.
// ---------------------------------------------------------------------------
#define ZBLK 6250   // ceil(1.6e6 / 256)
#define WBLK 224    // ceil(57344 / 256)
__global__ void prep_kernel(const float* __restrict__ W1, const float* __restrict__ W2,
                            const float* __restrict__ W3, const float* __restrict__ W4) {
    if (blockIdx.x < ZBLK) {
        int i = blockIdx.x * blockDim.x + threadIdx.x;
        if (i < N_NODES * 16) g_agg[i] = make_float4(0.f, 0.f, 0.f, 0.f);
        if (i < N_NODES) g_deg[i] = 0.0f;
        return;
    }
    int i = (blockIdx.x - ZBLK) * blockDim.x + threadIdx.x;
    const float* W; int MOUT; int base; int idx;
    if      (i < 16384) { W = W1; MOUT = 128; base = 0;     idx = i; }
    else if (i < 32768) { W = W2; MOUT = 128; base = 16384; idx = i - 16384; }
    else if (i < 49152) { W = W3; MOUT = 128; base = 32768; idx = i - 32768; }
    else if (i < 57344) { W = W4; MOUT = 64;  base = 49152; idx = i - 49152; }
    else return;
    int k = idx / MOUT, n = idx % MOUT;
    float v = W[idx];
    int off = base + n * 128 + k;        // bf16 element offset
    __nv_bfloat16 h = __float2bfloat16(v);
    ((__nv_bfloat16*)g_Whi)[off] = h;
    ((__nv_bfloat16*)g_Wlo)[off] = __float2bfloat16(v - __bfloat162float(h));
}

// ---------------------------------------------------------------------------
// Edge scatter: agg[row] += x[col] (RED.v4), deg[row] += 1
// ---------------------------------------------------------------------------
__global__ void scatter_kernel(const int* __restrict__ ei,
                               const float* __restrict__ x) {
    int t = blockIdx.x * blockDim.x + threadIdx.x;
    if (t >= N_EDGES * 16) return;
    int e = t >> 4;
    int c = t & 15;
    int dst = ei[e];
    int src = ei[N_EDGES + e];
    if ((unsigned)dst >= N_NODES || (unsigned)src >= N_NODES) return;
    const float4* x4 = (const float4*)x;
    float4 v = __ldg(&x4[src * 16 + c]);
    float4* p = &g_agg[dst * 16 + c];
    asm volatile("red.global.add.v4.f32 [%0], {%1, %2, %3, %4};"
                 :: "l"(p), "f"(v.x), "f"(v.y), "f"(v.z), "f"(v.w) : "memory");
    if (c == 0) atomicAdd(&g_deg[dst], 1.0f);
}

// ---------------------------------------------------------------------------
// One MLP layer executed in-smem, 16 warps (4x4 warp grid).
// Warp tile: 32 rows x (MOUT/4) cols. Split-bf16: D = Ah*Bh + Al*Bh + Ah*Bl.
// P = p-iterations (16 cols each): 2 for MOUT=128, 1 for MOUT=64.
// ---------------------------------------------------------------------------
template <int MOUT, bool RELU, bool LAST>
__device__ __forceinline__ void layer_step(
    char* smem, u32 sb,
    const float4* __restrict__ Wh, const float4* __restrict__ Wl,
    const float* __restrict__ bias, float* __restrict__ out, int tile)
{
    constexpr int P = MOUT / 64;           // p iters per warp
    const int tid = threadIdx.x;

    // ---- stage W hi/lo + bias ----
    {
        constexpr int BF4 = MOUT * 16;
#pragma unroll
        for (int i = tid; i < BF4; i += NTHREADS) {
            int row = i >> 4, seg = i & 15;
            *(float4*)(smem + W_HI + row * SROW + seg * 16) = Wh[i];
            *(float4*)(smem + W_LO + row * SROW + seg * 16) = Wl[i];
        }
        if (tid < MOUT) ((float*)(smem + BIAS))[tid] = bias[tid];
    }
    __syncthreads();

    const int lane = tid & 31, w = tid >> 5;
    const int m0 = (w & 3) * 32;
    const int n0 = (w >> 2) * (MOUT / 4);
    const u32 frag_off = (u32)((lane & 15) * SROW + (lane >> 4) * 16);

    float acc[2][2 * P][4];
#pragma unroll
    for (int mt = 0; mt < 2; mt++)
#pragma unroll
        for (int nt = 0; nt < 2 * P; nt++)
#pragma unroll
            for (int q = 0; q < 4; q++) acc[mt][nt][q] = 0.0f;

    const u32 aHi0 = sb + A_HI + m0 * SROW + frag_off;
    const u32 aLo0 = sb + A_LO + m0 * SROW + frag_off;
    const u32 bHi0 = sb + W_HI + n0 * SROW + frag_off;
    const u32 bLo0 = sb + W_LO + n0 * SROW + frag_off;

#pragma unroll
    for (int ks = 0; ks < 8; ks++) {
        const u32 koff = ks * 32;        // 16 bf16 = 32 bytes
        u32 ah[2][4], al[2][4];
#pragma unroll
        for (int mt = 0; mt < 2; mt++) {
            LDSM_X4(ah[mt][0], ah[mt][1], ah[mt][2], ah[mt][3],
                    aHi0 + mt * 16 * SROW + koff);
            LDSM_X4(al[mt][0], al[mt][1], al[mt][2], al[mt][3],
                    aLo0 + mt * 16 * SROW + koff);
        }
#pragma unroll
        for (int p = 0; p < P; p++) {
            u32 bh[4], bl[4];
            LDSM_X4(bh[0], bh[1], bh[2], bh[3], bHi0 + p * 16 * SROW + koff);
            LDSM_X4(bl[0], bl[1], bl[2], bl[3], bLo0 + p * 16 * SROW + koff);
#pragma unroll
            for (int mt = 0; mt < 2; mt++) {
                MMA16816(acc[mt][2*p],   ah[mt], bh[0], bh[2]);
                MMA16816(acc[mt][2*p],   al[mt], bh[0], bh[2]);
                MMA16816(acc[mt][2*p],   ah[mt], bl[0], bl[2]);
                MMA16816(acc[mt][2*p+1], ah[mt], bh[1], bh[3]);
                MMA16816(acc[mt][2*p+1], al[mt], bh[1], bh[3]);
                MMA16816(acc[mt][2*p+1], ah[mt], bl[1], bl[3]);
            }
        }
    }
    __syncthreads();   // all A/W reads done; safe to overwrite A (and W next layer)

    // ---- epilogue ----
    const float* sbias = (const float*)(smem + BIAS);
#pragma unroll
    for (int mt = 0; mt < 2; mt++) {
#pragma unroll
        for (int nt = 0; nt < 2 * P; nt++) {
            int r0 = m0 + mt * 16 + (lane >> 2);
            int r1 = r0 + 8;
            int cg = n0 + nt * 8 + (lane & 3) * 2;
            float b0 = sbias[cg], b1 = sbias[cg + 1];
            float v0 = acc[mt][nt][0] + b0, v1 = acc[mt][nt][1] + b1;
            float v2 = acc[mt][nt][2] + b0, v3 = acc[mt][nt][3] + b1;
            if (RELU) {
                v0 = fmaxf(v0, 0.f); v1 = fmaxf(v1, 0.f);
                v2 = fmaxf(v2, 0.f); v3 = fmaxf(v3, 0.f);
            }
            if (LAST) {
                int gr0 = tile * 128 + r0, gr1 = tile * 128 + r1;
                if (gr0 < N_NODES)
                    *(float2*)(out + (size_t)gr0 * OUT_DIM + cg) = make_float2(v0, v1);
                if (gr1 < N_NODES)
                    *(float2*)(out + (size_t)gr1 * OUT_DIM + cg) = make_float2(v2, v3);
            } else {
                *(u32*)(smem + A_HI + r0 * SROW + cg * 2) = pack_hi(v0, v1);
                *(u32*)(smem + A_LO + r0 * SROW + cg * 2) =
                    pack_hi(v0 - bf16_rt(v0), v1 - bf16_rt(v1));
                *(u32*)(smem + A_HI + r1 * SROW + cg * 2) = pack_hi(v2, v3);
                *(u32*)(smem + A_LO + r1 * SROW + cg * 2) =
                    pack_hi(v2 - bf16_rt(v2), v3 - bf16_rt(v3));
            }
        }
    }
    // next layer's post-stage __syncthreads orders these writes before its reads
}

// ---------------------------------------------------------------------------
// Fused MLP: per 128-row tile, build h0 planes in smem, then 4 layers in-smem.
// ---------------------------------------------------------------------------
__global__ __launch_bounds__(NTHREADS, 1) void fused_mlp(
    const float* __restrict__ x,
    const float4* __restrict__ Wh, const float4* __restrict__ Wl,
    const float* __restrict__ b1, const float* __restrict__ b2,
    const float* __restrict__ b3, const float* __restrict__ b4,
    float* __restrict__ out)
{
    extern __shared__ char smem[];
    const u32 sb = smem_u32(smem);
    const int tid = threadIdx.x;
    const int tile = blockIdx.x;

    // ---- prologue: h0 = concat(x, agg/max(deg,1)) -> bf16 hi/lo planes in smem
    const float4* x4 = (const float4*)x;
#pragma unroll
    for (int i = tid; i < 128 * 16; i += NTHREADS) {
        int r = i >> 4;
        int c0 = (i & 15) * 8;
        int gr = tile * 128 + r;
        float v[8];
        if (gr < N_NODES) {
            if (c0 < 64) {
                float4 a = x4[(size_t)gr * 16 + c0 / 4];
                float4 b = x4[(size_t)gr * 16 + c0 / 4 + 1];
                v[0]=a.x; v[1]=a.y; v[2]=a.z; v[3]=a.w;
                v[4]=b.x; v[5]=b.y; v[6]=b.z; v[7]=b.w;
            } else {
                float inv = 1.0f / fmaxf(g_deg[gr], 1.0f);
                float4 a = g_agg[(size_t)gr * 16 + (c0 - 64) / 4];
                float4 b = g_agg[(size_t)gr * 16 + (c0 - 64) / 4 + 1];
                v[0]=a.x*inv; v[1]=a.y*inv; v[2]=a.z*inv; v[3]=a.w*inv;
                v[4]=b.x*inv; v[5]=b.y*inv; v[6]=b.z*inv; v[7]=b.w*inv;
            }
        } else {
#pragma unroll
            for (int q = 0; q < 8; q++) v[q] = 0.0f;
        }
        u32 hw[4], lw[4];
#pragma unroll
        for (int q = 0; q < 4; q++) {
            float a = v[2*q], b = v[2*q+1];
            hw[q] = pack_hi(a, b);
            lw[q] = pack_hi(a - bf16_rt(a), b - bf16_rt(b));
        }
        *(float4*)(smem + A_HI + r * SROW + c0 * 2) = *(float4*)hw;
        *(float4*)(smem + A_LO + r * SROW + c0 * 2) = *(float4*)lw;
    }
    // (layer_step's post-stage __syncthreads orders the prologue writes too)

    layer_step<128, true,  false>(smem, sb, Wh + 0,    Wl + 0,    b1, nullptr, tile);
    layer_step<128, true,  false>(smem, sb, Wh + 2048, Wl + 2048, b2, nullptr, tile);
    layer_step<128, true,  false>(smem, sb, Wh + 4096, Wl + 4096, b3, nullptr, tile);
    layer_step<64,  false, true >(smem, sb, Wh + 6144, Wl + 6144, b4, out,     tile);
}

// ---------------------------------------------------------------------------
extern "C" void kernel_launch(void* const* d_in, const int* in_sizes, int n_in,
                              void* d_out, int out_size) {
    const float* x  = (const float*)d_in[0];
    const int*   ei = (const int*)d_in[1];
    const float* W1 = (const float*)d_in[2];
    const float* b1 = (const float*)d_in[3];
    const float* W2 = (const float*)d_in[4];
    const float* b2 = (const float*)d_in[5];
    const float* W3 = (const float*)d_in[6];
    const float* b3 = (const float*)d_in[7];
    const float* W4 = (const float*)d_in[8];
    const float* b4 = (const float*)d_in[9];
    float* out      = (float*)d_out;

    void *whp, *wlp;
    cudaGetSymbolAddress(&whp, g_Whi);
    cudaGetSymbolAddress(&wlp, g_Wlo);
    float4* Wh = (float4*)whp;
    float4* Wl = (float4*)wlp;

    cudaFuncSetAttribute(fused_mlp,
                         cudaFuncAttributeMaxDynamicSharedMemorySize, SMEM_TOTAL);

    prep_kernel<<<ZBLK + WBLK, 256>>>(W1, W2, W3, W4);
    scatter_kernel<<<(N_EDGES * 16 + 255) / 256, 256>>>(ei, x);
    fused_mlp<<<NT, NTHREADS, SMEM_TOTAL>>>(x, Wh, Wl, b1, b2, b3, b4, out);
}

// round 17
// speedup vs baseline: 3.3436x; 1.1383x over previous
#include <cuda_runtime.h>
#include <cuda_bf16.h>

#define N_NODES 100000
#define N_EDGES 1250000
#define IN_DIM 64
#define HID 128
#define OUT_DIM 64
#define NT 782                 // row tiles of 128: 782*128 = 100096 >= N_NODES

typedef unsigned int u32;

// ---------------------------------------------------------------------------
// Device scratch (zero-initialized at load).
// ---------------------------------------------------------------------------
__device__ float4 g_agg[N_NODES * IN_DIM / 4];
__device__ float  g_deg[N_NODES];
// weight plane images Wt[n][k] bf16 hi/lo: W1@0, W2@2048, W3@4096, W4@6144 (float4)
__device__ float4 g_Whi[3 * 2048 + 1024], g_Wlo[3 * 2048 + 1024];
// fragment-ordered weights: [layer base][c][ks][lane][4 u32]
// layer bases (u32): L1=0, L2=8192, L3=16384, L4=24576 ; total 28672 u32/plane
__device__ uint4 g_fWhi[28672 / 4], g_fWlo[28672 / 4];

// ---------------------------------------------------------------------------
__device__ __forceinline__ u32 smem_u32(const void* p) {
    u32 a;
    asm("{ .reg .u64 t; cvta.to.shared.u64 t, %1; cvt.u32.u64 %0, t; }"
        : "=r"(a) : "l"(p));
    return a;
}
__device__ __forceinline__ u32 pack_hi(float a, float b) {
    __nv_bfloat162 p;
    p.x = __float2bfloat16(a); p.y = __float2bfloat16(b);
    return reinterpret_cast<u32&>(p);
}
__device__ __forceinline__ float bf16_rt(float v) {
    return __bfloat162float(__float2bfloat16(v));
}

#define LDSM_X4(r0, r1, r2, r3, addr)                                          \
    asm volatile("ldmatrix.sync.aligned.m8n8.x4.shared.b16 {%0,%1,%2,%3}, [%4];" \
                 : "=r"(r0), "=r"(r1), "=r"(r2), "=r"(r3) : "r"(addr))

#define MMA16816(d, a, b0, b1)                                                 \
    asm volatile("mma.sync.aligned.m16n8k16.row.col.f32.bf16.bf16.f32 "        \
                 "{%0,%1,%2,%3}, {%4,%5,%6,%7}, {%8,%9}, {%0,%1,%2,%3};"       \
                 : "+f"((d)[0]), "+f"((d)[1]), "+f"((d)[2]), "+f"((d)[3])      \
                 : "r"((a)[0]), "r"((a)[1]), "r"((a)[2]), "r"((a)[3]),         \
                   "r"(b0), "r"(b1))

// smem: A planes only. SROW = 272 (136 bf16) -> conflict-free ldmatrix
#define SROW 272
#define A_HI 0
#define A_LO (128 * SROW)                 // 34816
#define SMEM_TOTAL (2 * 128 * SROW)       // 69632  -> 2 CTAs/SM

// ---------------------------------------------------------------------------
// prep1: zero accumulators (blocks [0, ZBLK)) + weight plane conversion.
// ---------------------------------------------------------------------------
#define ZBLK 6250   // ceil(1.6e6 / 256)
#define WBLK 224    // ceil(57344 / 256)
__global__ void prep1_kernel(const float* __restrict__ W1, const float* __restrict__ W2,
                             const float* __restrict__ W3, const float* __restrict__ W4) {
    if (blockIdx.x < ZBLK) {
        int i = blockIdx.x * blockDim.x + threadIdx.x;
        if (i < N_NODES * 16) g_agg[i] = make_float4(0.f, 0.f, 0.f, 0.f);
        if (i < N_NODES) g_deg[i] = 0.0f;
        return;
    }
    int i = (blockIdx.x - ZBLK) * blockDim.x + threadIdx.x;
    const float* W; int MOUT; int base; int idx;
    if      (i < 16384) { W = W1; MOUT = 128; base = 0;     idx = i; }
    else if (i < 32768) { W = W2; MOUT = 128; base = 16384; idx = i - 16384; }
    else if (i < 49152) { W = W3; MOUT = 128; base = 32768; idx = i - 32768; }
    else if (i < 57344) { W = W4; MOUT = 64;  base = 49152; idx = i - 49152; }
    else return;
    int k = idx / MOUT, n = idx % MOUT;
    float v = W[idx];
    int off = base + n * 128 + k;        // bf16 element offset
    __nv_bfloat16 h = __float2bfloat16(v);
    ((__nv_bfloat16*)g_Whi)[off] = h;
    ((__nv_bfloat16*)g_Wlo)[off] = __float2bfloat16(v - __bfloat162float(h));
}

// ---------------------------------------------------------------------------
// prep2: reorder planes into fragment order via the SAME ldmatrix the old
// mainloop used -> bit-identical fragments, zero derivation risk.
// Block = (plane, layer, c): stage Wt rows [c*16,(c+1)*16) x k128 into smem
// (SROW layout), then warp ws handles ks=ws: LDSM_X4 -> store 4 regs linear.
// 28 (layer,c) combos per plane, 56 blocks total.
// ---------------------------------------------------------------------------
__global__ void prep2_kernel() {
    __shared__ __align__(16) char smem[16 * SROW];
    const int tid = threadIdx.x;
    int b = blockIdx.x;
    int plane = b / 28;
    int combo = b % 28;
    int l = (combo < 24) ? (combo >> 3) : 3;
    int c = (combo < 24) ? (combo & 7) : (combo - 24);
    // plane source base (float4 units) and frag dest base (uint4 units)
    const int planeBaseF4[4] = { 0, 2048, 4096, 6144 };
    const int fragBaseU4[4]  = { 0, 2048, 4096, 6144 };  // u32/4
    const float4* src = (plane == 0 ? g_Whi : g_Wlo);
    uint4* dst = (plane == 0 ? g_fWhi : g_fWlo);

    // stage 16 rows x 128 k (16 float4 per row)
    {
        int r = tid >> 4, seg = tid & 15;   // 256 threads exactly
        *(float4*)(smem + r * SROW + seg * 16) =
            src[planeBaseF4[l] + (c * 16 + r) * 16 + seg];
    }
    __syncthreads();

    const u32 sb = smem_u32(smem);
    const int lane = tid & 31, ws = tid >> 5;   // ws = ks
    const u32 addr = sb + (u32)((lane & 15) * SROW + (lane >> 4) * 16) + ws * 32;
    u32 r0, r1, r2, r3;
    LDSM_X4(r0, r1, r2, r3, addr);
    dst[fragBaseU4[l] + c * 256 + ws * 32 + lane] = make_uint4(r0, r1, r2, r3);
}

// ---------------------------------------------------------------------------
// Edge scatter: agg[row] += x[col] (RED.v4), deg[row] += 1
// ---------------------------------------------------------------------------
__global__ void scatter_kernel(const int* __restrict__ ei,
                               const float* __restrict__ x) {
    int t = blockIdx.x * blockDim.x + threadIdx.x;
    if (t >= N_EDGES * 16) return;
    int e = t >> 4;
    int c = t & 15;
    int dst = ei[e];
    int src = ei[N_EDGES + e];
    if ((unsigned)dst >= N_NODES || (unsigned)src >= N_NODES) return;
    const float4* x4 = (const float4*)x;
    float4 v = __ldg(&x4[src * 16 + c]);
    float4* p = &g_agg[dst * 16 + c];
    asm volatile("red.global.add.v4.f32 [%0], {%1, %2, %3, %4};"
                 :: "l"(p), "f"(v.x), "f"(v.y), "f"(v.z), "f"(v.w) : "memory");
    if (c == 0) atomicAdd(&g_deg[dst], 1.0f);
}

// ---------------------------------------------------------------------------
// One MLP layer: A planes in smem, B fragments via LDG from g_fW* (L1/L2-hot).
// 8 warps (4x2): warp tile 32 rows x MOUT/2 cols; P = MOUT/32 p-iters.
// Split-bf16: D = Ah*Bh + Al*Bh + Ah*Bl.
// ---------------------------------------------------------------------------
template <int MOUT, bool RELU, bool LAST>
__device__ __forceinline__ void layer_step(
    char* smem, u32 sb, int fragBase,
    const float* __restrict__ bias, float* __restrict__ out, int tile)
{
    constexpr int P = MOUT / 32;
    const int tid = threadIdx.x;
    const int lane = tid & 31, w = tid >> 5;
    const int m0 = (w & 3) * 32;
    const int n0 = (w >> 2) * (MOUT / 2);
    const u32 frag_off = (u32)((lane & 15) * SROW + (lane >> 4) * 16);

    float acc[2][2 * P][4];
#pragma unroll
    for (int mt = 0; mt < 2; mt++)
#pragma unroll
        for (int nt = 0; nt < 2 * P; nt++)
#pragma unroll
            for (int q = 0; q < 4; q++) acc[mt][nt][q] = 0.0f;

    const u32 aHi0 = sb + A_HI + m0 * SROW + frag_off;
    const u32 aLo0 = sb + A_LO + m0 * SROW + frag_off;
    const uint4* fh = g_fWhi + fragBase + (n0 / 16) * 256 + lane;
    const uint4* fl = g_fWlo + fragBase + (n0 / 16) * 256 + lane;

#pragma unroll
    for (int ks = 0; ks < 8; ks++) {
        const u32 koff = ks * 32;        // 16 bf16 = 32 bytes
        u32 ah[2][4], al[2][4];
#pragma unroll
        for (int mt = 0; mt < 2; mt++) {
            LDSM_X4(ah[mt][0], ah[mt][1], ah[mt][2], ah[mt][3],
                    aHi0 + mt * 16 * SROW + koff);
            LDSM_X4(al[mt][0], al[mt][1], al[mt][2], al[mt][3],
                    aLo0 + mt * 16 * SROW + koff);
        }
#pragma unroll
        for (int p = 0; p < P; p++) {
            uint4 bh = __ldg(fh + p * 256 + ks * 32);
            uint4 bl = __ldg(fl + p * 256 + ks * 32);
#pragma unroll
            for (int mt = 0; mt < 2; mt++) {
                MMA16816(acc[mt][2*p],   ah[mt], bh.x, bh.z);
                MMA16816(acc[mt][2*p],   al[mt], bh.x, bh.z);
                MMA16816(acc[mt][2*p],   ah[mt], bl.x, bl.z);
                MMA16816(acc[mt][2*p+1], ah[mt], bh.y, bh.w);
                MMA16816(acc[mt][2*p+1], al[mt], bh.y, bh.w);
                MMA16816(acc[mt][2*p+1], ah[mt], bl.y, bl.w);
            }
        }
    }
    __syncthreads();   // all A reads done; safe to overwrite A planes

    // ---- epilogue ----
#pragma unroll
    for (int mt = 0; mt < 2; mt++) {
#pragma unroll
        for (int nt = 0; nt < 2 * P; nt++) {
            int r0 = m0 + mt * 16 + (lane >> 2);
            int r1 = r0 + 8;
            int cg = n0 + nt * 8 + (lane & 3) * 2;
            float b0 = __ldg(bias + cg), b1 = __ldg(bias + cg + 1);
            float v0 = acc[mt][nt][0] + b0, v1 = acc[mt][nt][1] + b1;
            float v2 = acc[mt][nt][2] + b0, v3 = acc[mt][nt][3] + b1;
            if (RELU) {
                v0 = fmaxf(v0, 0.f); v1 = fmaxf(v1, 0.f);
                v2 = fmaxf(v2, 0.f); v3 = fmaxf(v3, 0.f);
            }
            if (LAST) {
                int gr0 = tile * 128 + r0, gr1 = tile * 128 + r1;
                if (gr0 < N_NODES)
                    *(float2*)(out + (size_t)gr0 * OUT_DIM + cg) = make_float2(v0, v1);
                if (gr1 < N_NODES)
                    *(float2*)(out + (size_t)gr1 * OUT_DIM + cg) = make_float2(v2, v3);
            } else {
                *(u32*)(smem + A_HI + r0 * SROW + cg * 2) = pack_hi(v0, v1);
                *(u32*)(smem + A_LO + r0 * SROW + cg * 2) =
                    pack_hi(v0 - bf16_rt(v0), v1 - bf16_rt(v1));
                *(u32*)(smem + A_HI + r1 * SROW + cg * 2) = pack_hi(v2, v3);
                *(u32*)(smem + A_LO + r1 * SROW + cg * 2) =
                    pack_hi(v2 - bf16_rt(v2), v3 - bf16_rt(v3));
            }
        }
    }
    __syncthreads();   // epilogue writes visible before next layer's reads
}

// ---------------------------------------------------------------------------
// Fused MLP: per 128-row tile, build h0 planes in smem, then 4 layers.
// ---------------------------------------------------------------------------
__global__ __launch_bounds__(256, 2) void fused_mlp(
    const float* __restrict__ x,
    const float* __restrict__ b1, const float* __restrict__ b2,
    const float* __restrict__ b3, const float* __restrict__ b4,
    float* __restrict__ out)
{
    extern __shared__ char smem[];
    const u32 sb = smem_u32(smem);
    const int tid = threadIdx.x;
    const int tile = blockIdx.x;

    // ---- prologue: h0 = concat(x, agg/max(deg,1)) -> bf16 hi/lo planes
    const float4* x4 = (const float4*)x;
#pragma unroll
    for (int i = tid; i < 128 * 16; i += 256) {
        int r = i >> 4;
        int c0 = (i & 15) * 8;
        int gr = tile * 128 + r;
        float v[8];
        if (gr < N_NODES) {
            if (c0 < 64) {
                float4 a = x4[(size_t)gr * 16 + c0 / 4];
                float4 b = x4[(size_t)gr * 16 + c0 / 4 + 1];
                v[0]=a.x; v[1]=a.y; v[2]=a.z; v[3]=a.w;
                v[4]=b.x; v[5]=b.y; v[6]=b.z; v[7]=b.w;
            } else {
                float inv = 1.0f / fmaxf(g_deg[gr], 1.0f);
                float4 a = g_agg[(size_t)gr * 16 + (c0 - 64) / 4];
                float4 b = g_agg[(size_t)gr * 16 + (c0 - 64) / 4 + 1];
                v[0]=a.x*inv; v[1]=a.y*inv; v[2]=a.z*inv; v[3]=a.w*inv;
                v[4]=b.x*inv; v[5]=b.y*inv; v[6]=b.z*inv; v[7]=b.w*inv;
            }
        } else {
#pragma unroll
            for (int q = 0; q < 8; q++) v[q] = 0.0f;
        }
        u32 hw[4], lw[4];
#pragma unroll
        for (int q = 0; q < 4; q++) {
            float a = v[2*q], b = v[2*q+1];
            hw[q] = pack_hi(a, b);
            lw[q] = pack_hi(a - bf16_rt(a), b - bf16_rt(b));
        }
        *(float4*)(smem + A_HI + r * SROW + c0 * 2) = *(float4*)hw;
        *(float4*)(smem + A_LO + r * SROW + c0 * 2) = *(float4*)lw;
    }
    __syncthreads();

    layer_step<128, true,  false>(smem, sb, 0,    b1, nullptr, tile);
    layer_step<128, true,  false>(smem, sb, 2048, b2, nullptr, tile);
    layer_step<128, true,  false>(smem, sb, 4096, b3, nullptr, tile);
    layer_step<64,  false, true >(smem, sb, 6144, b4, out,     tile);
}

// ---------------------------------------------------------------------------
extern "C" void kernel_launch(void* const* d_in, const int* in_sizes, int n_in,
                              void* d_out, int out_size) {
    const float* x  = (const float*)d_in[0];
    const int*   ei = (const int*)d_in[1];
    const float* W1 = (const float*)d_in[2];
    const float* b1 = (const float*)d_in[3];
    const float* W2 = (const float*)d_in[4];
    const float* b2 = (const float*)d_in[5];
    const float* W3 = (const float*)d_in[6];
    const float* b3 = (const float*)d_in[7];
    const float* W4 = (const float*)d_in[8];
    const float* b4 = (const float*)d_in[9];
    float* out      = (float*)d_out;

    cudaFuncSetAttribute(fused_mlp,
                         cudaFuncAttributeMaxDynamicSharedMemorySize, SMEM_TOTAL);

    prep1_kernel<<<ZBLK + WBLK, 256>>>(W1, W2, W3, W4);
    prep2_kernel<<<56, 256>>>();
    scatter_kernel<<<(N_EDGES * 16 + 255) / 256, 256>>>(ei, x);
    fused_mlp<<<NT, 256, SMEM_TOTAL>>>(x, b1, b2, b3, b4, out);
}